// round 14
// baseline (speedup 1.0000x reference)
#include <cuda_runtime.h>
#include <cuda_fp16.h>
#include <cstdint>
#include <cstddef>

#define NATOMS 16384
#define NEDGES 32768
#define NMOLS  512
#define DV     72
#define DE     14
#define DH     2048

#define KPAD_I 128
#define KPAD_O 2176

// ---------------- scratch ----------------
__device__ __half g_H0h[(size_t)NEDGES * DH];   // H0 (fp16)
__device__ __half g_HFA[(size_t)NEDGES * DH];   // H ping
__device__ __half g_HFB[(size_t)NEDGES * DH];   // H pong
__device__ float  g_MA[(size_t)NATOMS * DH];    // MAT ping
__device__ float  g_MB[(size_t)NATOMS * DH];    // MAT pong
__device__ __half g_AH[(size_t)NEDGES * DH];    // fp16 A operand
__device__ __half g_Wi[(size_t)KPAD_I * DH];
__device__ __half g_Wh[(size_t)DH * DH];
__device__ __half g_Wo[(size_t)KPAD_O * DH];

// ---------------- helpers ----------------
__device__ __forceinline__ uint32_t smem_u32(const void* p) {
    uint32_t a;
    asm("{ .reg .u64 t; cvta.to.shared.u64 t, %1; cvt.u32.u64 %0, t; }" : "=r"(a) : "l"(p));
    return a;
}
__device__ __forceinline__ void ldm_x4(uint32_t* r, uint32_t addr) {
    asm volatile("ldmatrix.sync.aligned.m8n8.x4.shared.b16 {%0,%1,%2,%3}, [%4];"
                 : "=r"(r[0]), "=r"(r[1]), "=r"(r[2]), "=r"(r[3]) : "r"(addr));
}
__device__ __forceinline__ void ldm_x2t(uint32_t* r, uint32_t addr) {
    asm volatile("ldmatrix.sync.aligned.m8n8.x2.trans.shared.b16 {%0,%1}, [%2];"
                 : "=r"(r[0]), "=r"(r[1]) : "r"(addr));
}
__device__ __forceinline__ void mma_f16(float* d, const uint32_t* a, const uint32_t* b) {
    asm volatile("mma.sync.aligned.m16n8k16.row.col.f32.f16.f16.f32 "
                 "{%0,%1,%2,%3}, {%4,%5,%6,%7}, {%8,%9}, {%0,%1,%2,%3};"
                 : "+f"(d[0]), "+f"(d[1]), "+f"(d[2]), "+f"(d[3])
                 : "r"(a[0]), "r"(a[1]), "r"(a[2]), "r"(a[3]), "r"(b[0]), "r"(b[1]));
}
__device__ __forceinline__ void cp16(uint32_t dst, const void* src) {
    asm volatile("cp.async.cg.shared.global [%0], [%1], 16;" :: "r"(dst), "l"(src) : "memory");
}
#define CP_COMMIT() asm volatile("cp.async.commit_group;" ::: "memory")
#define CP_WAIT2()  asm volatile("cp.async.wait_group 2;" ::: "memory")

__device__ __forceinline__ uint32_t pack_h2(float x0, float x1) {
    __half2 h = __halves2half2(__float2half_rn(x0), __float2half_rn(x1));
    return *reinterpret_cast<uint32_t*>(&h);
}
__device__ __forceinline__ float2 unpack_h2(uint32_t u) {
    __half2 h = *reinterpret_cast<__half2*>(&u);
    return __half22float2(h);
}

// ---------------- GEMM geometry ----------------
// BM=128, BN=256, BK=64, 256 threads (8 warps, 2m x 4n, warp tile 64x64)
#define A_PITCH 144
#define B_PITCH 528
#define A_BYTES (128 * A_PITCH)          // 18432
#define STAGE_B (A_BYTES + 64 * B_PITCH) // 52224
#define SMEM_TOTAL (4 * STAGE_B)         // 208896

// ---------------------------------------------------------------------------
// Dense fp16 GEMM with fused epilogues.
// MODE 0: v=relu(acc)        -> [STOREH] Hout f16 + fp32 atomicAdd MATnext[dst]
// MODE 1: v=relu(H0h+acc)    -> [STOREH] Hout f16 + fp32 atomicAdd MATnext[dst]
// MODE 2: v=relu(acc+bias)   -> smem-reduced molecule mean -> atomicAdd Fout
// ---------------------------------------------------------------------------
template <int MODE, int KPAD, bool STOREH>
__global__ __launch_bounds__(256, 1)
void mma_gemm(const __half* __restrict__ AH, const __half* __restrict__ W,
              const __half* __restrict__ EPh, const float* __restrict__ bias,
              const int* __restrict__ dst, float* __restrict__ MATnext,
              __half* __restrict__ Hout, float* __restrict__ Fout)
{
    constexpr int NT = KPAD / 64;
    extern __shared__ char smem[];
    __shared__ int s_dst[128];
    const uint32_t sb = smem_u32(smem);
    const int tid = threadIdx.x;
    const int wid = tid >> 5, lane = tid & 31;
    const int wm = wid >> 2, wn = wid & 3;
    const int m0 = blockIdx.y * 128, n0 = blockIdx.x * 256;

    if (MODE != 2 && tid < 128) s_dst[tid] = dst[m0 + tid];

    float acc[4][8][4];
#pragma unroll
    for (int i = 0; i < 4; i++)
#pragma unroll
        for (int j = 0; j < 8; j++)
#pragma unroll
            for (int c = 0; c < 4; c++) acc[i][j][c] = 0.f;

    // ---- async fill of one stage with chunk u ----
    auto issue = [&](int u, int stage) {
        const int kk = u * 64;
        const uint32_t ab = sb + stage * STAGE_B;
        const uint32_t bb = ab + A_BYTES;
#pragma unroll
        for (int p = 0; p < 4; p++) {            // A: 1024 x 16B units
            const int u2 = p * 256 + tid;
            const int row = u2 >> 3, cu = u2 & 7;
            cp16(ab + row * A_PITCH + cu * 16,
                 AH + (size_t)(m0 + row) * KPAD + kk + cu * 8);
        }
#pragma unroll
        for (int p = 0; p < 8; p++) {            // B: 2048 x 16B units
            const int u2 = p * 256 + tid;
            const int row = u2 >> 5, cu = u2 & 31;
            cp16(bb + row * B_PITCH + cu * 16,
                 W + (size_t)(kk + row) * DH + n0 + cu * 8);
        }
    };

    // ---- compute one chunk from a stage ----
    auto compute = [&](int stage) {
        const uint32_t ab = sb + stage * STAGE_B;
        const uint32_t bb = ab + A_BYTES;
        const uint32_t aBase = ab + (uint32_t)(wm * 64 + (lane & 15)) * A_PITCH
                                  + (uint32_t)((lane >> 4) * 16);
        const uint32_t bBase = bb + (uint32_t)(lane & 15) * B_PITCH + (uint32_t)(wn * 128);
#pragma unroll
        for (int ks = 0; ks < 4; ks++) {
            uint32_t a[4][4], b[8][2];
#pragma unroll
            for (int mt = 0; mt < 4; mt++)
                ldm_x4(a[mt], aBase + mt * 16 * A_PITCH + ks * 32);
#pragma unroll
            for (int n = 0; n < 8; n++)
                ldm_x2t(b[n], bBase + ks * 16 * B_PITCH + n * 16);
#pragma unroll
            for (int mt = 0; mt < 4; mt++)
#pragma unroll
                for (int n = 0; n < 8; n++)
                    mma_f16(acc[mt][n], a[mt], b[n]);
        }
    };

    // prologue: up to 3 chunks in flight (4 stages)
    issue(0, 0); CP_COMMIT();
    if (1 < NT) issue(1, 1);
    CP_COMMIT();
    if (2 < NT) issue(2, 2);
    CP_COMMIT();

    for (int t = 0; t < NT; t++) {
        CP_WAIT2();
        __syncthreads();
        if (t + 3 < NT) issue(t + 3, (t + 3) & 3);
        CP_COMMIT();
        compute(t & 3);
    }

    // ---- fused epilogue ----
    const int r0 = lane >> 2, c0 = (lane & 3) * 2;
    if (MODE == 2) {
        // molecule-mean reduction: 128 rows = 4 molecules of 32 atoms
        __syncthreads();                          // pipeline smem now dead
        float* s_mean = reinterpret_cast<float*>(smem);   // 4 x 256 floats
        for (int i = tid; i < 1024; i += 256) s_mean[i] = 0.f;
        __syncthreads();
#pragma unroll
        for (int mt = 0; mt < 4; mt++) {
#pragma unroll
            for (int n = 0; n < 8; n++) {
                const int lr = wm * 64 + mt * 16 + r0;
                const int cl = wn * 64 + n * 8 + c0;
                float v0 = acc[mt][n][0], v1 = acc[mt][n][1];
                float v2 = acc[mt][n][2], v3 = acc[mt][n][3];
                float2 b = *reinterpret_cast<const float2*>(bias + n0 + cl);
                v0 += b.x; v1 += b.y; v2 += b.x; v3 += b.y;
                v0 = v0 > 0.f ? v0 : 0.f; v1 = v1 > 0.f ? v1 : 0.f;
                v2 = v2 > 0.f ? v2 : 0.f; v3 = v3 > 0.f ? v3 : 0.f;
                const int g0 = (lr >> 5) * 256, g1 = ((lr + 8) >> 5) * 256;
                atomicAdd(&s_mean[g0 + cl],     v0);
                atomicAdd(&s_mean[g0 + cl + 1], v1);
                atomicAdd(&s_mean[g1 + cl],     v2);
                atomicAdd(&s_mean[g1 + cl + 1], v3);
            }
        }
        __syncthreads();
        const int mol0 = m0 >> 5;                 // first molecule of this CTA
        for (int i = tid; i < 1024; i += 256) {
            const int g = i >> 8, cl = i & 255;
            atomicAdd(Fout + (size_t)(mol0 + g) * DH + n0 + cl,
                      s_mean[i] * (1.f / 32.f));
        }
        return;
    }
#pragma unroll
    for (int mt = 0; mt < 4; mt++) {
#pragma unroll
        for (int n = 0; n < 8; n++) {
            const int lr = wm * 64 + mt * 16 + r0;   // local row 0..127
            const int row = m0 + lr;
            const int col = n0 + wn * 64 + n * 8 + c0;
            float v0 = acc[mt][n][0], v1 = acc[mt][n][1];
            float v2 = acc[mt][n][2], v3 = acc[mt][n][3];
            if (MODE == 1) {
                float2 e0 = unpack_h2(*reinterpret_cast<const uint32_t*>(
                    EPh + (size_t)row * DH + col));
                float2 e1 = unpack_h2(*reinterpret_cast<const uint32_t*>(
                    EPh + (size_t)(row + 8) * DH + col));
                v0 += e0.x; v1 += e0.y; v2 += e1.x; v3 += e1.y;
            }
            v0 = v0 > 0.f ? v0 : 0.f; v1 = v1 > 0.f ? v1 : 0.f;
            v2 = v2 > 0.f ? v2 : 0.f; v3 = v3 > 0.f ? v3 : 0.f;
            if (STOREH) {
                *reinterpret_cast<uint32_t*>(Hout + (size_t)row * DH + col) = pack_h2(v0, v1);
                *reinterpret_cast<uint32_t*>(Hout + (size_t)(row + 8) * DH + col) = pack_h2(v2, v3);
            }
            const size_t d0 = (size_t)s_dst[lr] * DH + col;
            const size_t d1 = (size_t)s_dst[lr + 8] * DH + col;
            atomicAdd(MATnext + d0,     v0);
            atomicAdd(MATnext + d0 + 1, v1);
            atomicAdd(MATnext + d1,     v2);
            atomicAdd(MATnext + d1 + 1, v3);
        }
    }
}

// ---------------------------------------------------------------------------
// Prep kernels: materialize fp16 A operands
// ---------------------------------------------------------------------------
// MP: AH[e][k] = f16(MAT[src[e]][k] - Hh[rev[e]][k]); also zeroes MATnext.
__global__ void prep_mp_k(const float* __restrict__ MAT, const __half* __restrict__ H,
                          const int* __restrict__ src, const int* __restrict__ rev,
                          __half* __restrict__ AH, float* __restrict__ MATnext)
{
    int gid = blockIdx.x * blockDim.x + threadIdx.x;     // NEDGES * 512
    // fused zeroing of MATnext: NATOMS*DH/4 = 8388608 float4 stores
    if (gid < NATOMS * (DH / 4))
        reinterpret_cast<float4*>(MATnext)[gid] = make_float4(0.f, 0.f, 0.f, 0.f);
    int e = gid >> 9, c = gid & 511;
    float4 x = *reinterpret_cast<const float4*>(MAT + (size_t)__ldg(&src[e]) * DH + c * 4);
    uint2 yu = *reinterpret_cast<const uint2*>(H + (size_t)__ldg(&rev[e]) * DH + c * 4);
    float2 y0 = unpack_h2(yu.x), y1 = unpack_h2(yu.y);
    *reinterpret_cast<uint2*>(AH + (size_t)e * DH + c * 4) =
        make_uint2(pack_h2(x.x - y0.x, x.y - y0.y), pack_h2(x.z - y1.x, x.w - y1.y));
}
__global__ void prep_init_k(const float* __restrict__ V, const float* __restrict__ E,
                            const int* __restrict__ src, __half* __restrict__ AH)
{
    int gid = blockIdx.x * blockDim.x + threadIdx.x;     // NEDGES * 32
    int e = gid >> 5, c = gid & 31;
    const int k0 = c * 4;
    float v[4];
#pragma unroll
    for (int j = 0; j < 4; j++) {
        const int k = k0 + j;
        if (k < DV)           v[j] = V[(size_t)__ldg(&src[e]) * DV + k];
        else if (k < DV + DE) v[j] = E[(size_t)e * DE + (k - DV)];
        else                  v[j] = 0.f;
    }
    *reinterpret_cast<uint2*>(AH + (size_t)e * KPAD_I + k0) =
        make_uint2(pack_h2(v[0], v[1]), pack_h2(v[2], v[3]));
}
__global__ void prep_out_k(const float* __restrict__ V, const float* __restrict__ MV,
                           __half* __restrict__ AH)
{
    int gid = blockIdx.x * blockDim.x + threadIdx.x;     // NATOMS * 544
    if (gid >= NATOMS * (KPAD_O / 4)) return;
    int a = gid / (KPAD_O / 4), c = gid % (KPAD_O / 4);
    const int k0 = c * 4;
    float4 x;
    if (k0 < DV) {
        x = make_float4(V[(size_t)a * DV + k0], V[(size_t)a * DV + k0 + 1],
                        V[(size_t)a * DV + k0 + 2], V[(size_t)a * DV + k0 + 3]);
    } else if (k0 < DV + DH) {
        x = *reinterpret_cast<const float4*>(MV + (size_t)a * DH + (k0 - DV));
    } else {
        x = make_float4(0.f, 0.f, 0.f, 0.f);
    }
    *reinterpret_cast<uint2*>(AH + (size_t)a * KPAD_O + k0) =
        make_uint2(pack_h2(x.x, x.y), pack_h2(x.z, x.w));
}

// Weight convert to fp16 (keeps [K][2048] layout, zero-pads to Kpad rows)
__global__ void convert_w_k(const float* __restrict__ W,
                            __half* __restrict__ Oh, int K, int Kpad) {
    int idx = blockIdx.x * blockDim.x + threadIdx.x;
    int e0 = idx * 4;
    int k = e0 >> 11;
    if (k >= Kpad) return;
    float4 v = (k < K) ? *reinterpret_cast<const float4*>(W + e0)
                       : make_float4(0.f, 0.f, 0.f, 0.f);
    *reinterpret_cast<uint2*>(Oh + e0) =
        make_uint2(pack_h2(v.x, v.y), pack_h2(v.z, v.w));
}

// ---------------- aux kernels ----------------
__global__ void zero_k(float4* __restrict__ p, int n4) {
    int gid = blockIdx.x * blockDim.x + threadIdx.x;
    if (gid < n4) p[gid] = make_float4(0.f, 0.f, 0.f, 0.f);
}

extern "C" void kernel_launch(void* const* d_in, const int* in_sizes, int n_in,
                              void* d_out, int out_size)
{
    const float* V    = (const float*)d_in[0];
    const float* E    = (const float*)d_in[1];
    const int*   esrc = (const int*)d_in[2];
    const int*   edst = (const int*)d_in[3];
    const int*   erev = (const int*)d_in[4];
    const float* W_i  = (const float*)d_in[6];
    const float* W_h  = (const float*)d_in[7];
    const float* W_o  = (const float*)d_in[8];
    const float* b_o  = (const float*)d_in[9];
    float* out = (float*)d_out;

    float *MA, *MB;
    cudaGetSymbolAddress((void**)&MA, g_MA);
    cudaGetSymbolAddress((void**)&MB, g_MB);
    __half *H0h, *HFA, *HFB, *AH, *Wi, *Wh, *Wo;
    cudaGetSymbolAddress((void**)&H0h, g_H0h);
    cudaGetSymbolAddress((void**)&HFA, g_HFA);
    cudaGetSymbolAddress((void**)&HFB, g_HFB);
    cudaGetSymbolAddress((void**)&AH,  g_AH);
    cudaGetSymbolAddress((void**)&Wi,  g_Wi);
    cudaGetSymbolAddress((void**)&Wh,  g_Wh);
    cudaGetSymbolAddress((void**)&Wo,  g_Wo);

    cudaFuncSetAttribute(mma_gemm<0, KPAD_I, true>,
                         cudaFuncAttributeMaxDynamicSharedMemorySize, SMEM_TOTAL);
    cudaFuncSetAttribute(mma_gemm<1, DH, true>,
                         cudaFuncAttributeMaxDynamicSharedMemorySize, SMEM_TOTAL);
    cudaFuncSetAttribute(mma_gemm<1, DH, false>,
                         cudaFuncAttributeMaxDynamicSharedMemorySize, SMEM_TOTAL);
    cudaFuncSetAttribute(mma_gemm<2, KPAD_O, false>,
                         cudaFuncAttributeMaxDynamicSharedMemorySize, SMEM_TOTAL);

    const dim3 blk(256);
    convert_w_k<<<(KPAD_I * DH / 4 + 255) / 256, blk>>>(W_i, Wi, DV + DE, KPAD_I);
    convert_w_k<<<(DH * DH / 4 + 255) / 256, blk>>>(W_h, Wh, DH, DH);
    convert_w_k<<<(KPAD_O * DH / 4 + 255) / 256, blk>>>(W_o, Wo, DV + DH, KPAD_O);

    const dim3 gE(DH / 256, NEDGES / 128);   // (8, 256)
    const dim3 gA(DH / 256, NATOMS / 128);   // (8, 128)
    const int matN4  = NATOMS * (DH / 4);
    const int zeroBl = (matN4 + 255) / 256;

    // H0 = relu([V[src]; E] @ W_i); epilogue scatters H0 into MA
    prep_init_k<<<(NEDGES * 32) / 256, blk>>>(V, E, esrc, AH);
    zero_k<<<zeroBl, blk>>>((float4*)MA, matN4);
    mma_gemm<0, KPAD_I, true><<<gE, blk, SMEM_TOTAL>>>(AH, Wi, nullptr, nullptr,
                                                       edst, MA, H0h, nullptr);

    const __half* Hcur = H0h;
    for (int it = 0; it < 4; it++) {
        float* MATcur  = (it & 1) ? MB : MA;
        float* MATnext = (it & 1) ? MA : MB;
        __half* Hnext  = (it & 1) ? HFB : HFA;
        prep_mp_k<<<(NEDGES * 512) / 256, blk>>>(MATcur, Hcur, esrc, erev, AH, MATnext);
        if (it < 3)
            mma_gemm<1, DH, true><<<gE, blk, SMEM_TOTAL>>>(AH, Wh, H0h, nullptr,
                                                           edst, MATnext, Hnext, nullptr);
        else  // last MP layer: H output is dead, only the scatter matters
            mma_gemm<1, DH, false><<<gE, blk, SMEM_TOTAL>>>(AH, Wh, H0h, nullptr,
                                                            edst, MATnext, Hnext, nullptr);
        Hcur = Hnext;
    }

    // final MAT is MA; fingerprint = mean over molecules of relu([V;M_v]@W_o + b_o)
    prep_out_k<<<(NATOMS * (KPAD_O / 4) + 255) / 256, blk>>>(V, MA, AH);
    zero_k<<<(NMOLS * DH / 4 + 255) / 256, blk>>>((float4*)out, NMOLS * DH / 4);
    mma_gemm<2, KPAD_O, false><<<gA, blk, SMEM_TOTAL>>>(AH, Wo, nullptr, b_o,
                                                        nullptr, nullptr, nullptr, out);
}

// round 15
// speedup vs baseline: 1.0633x; 1.0633x over previous
#include <cuda_runtime.h>
#include <cuda_fp16.h>
#include <cstdint>
#include <cstddef>

#define NATOMS 16384
#define NEDGES 32768
#define NMOLS  512
#define DV     72
#define DE     14
#define DH     2048

#define KPAD_I 128
#define KPAD_O 2176

// ---------------- scratch ----------------
__device__ __half g_H0h[(size_t)NEDGES * DH];   // H0 (fp16)
__device__ __half g_HFA[(size_t)NEDGES * DH];   // H ping
__device__ __half g_HFB[(size_t)NEDGES * DH];   // H pong
__device__ float  g_MA[(size_t)NATOMS * DH];    // MAT ping
__device__ float  g_MB[(size_t)NATOMS * DH];    // MAT pong
__device__ __half g_AH[(size_t)NEDGES * DH];    // fp16 A operand
__device__ __half g_Wi[(size_t)KPAD_I * DH];
__device__ __half g_Wh[(size_t)DH * DH];
__device__ __half g_Wo[(size_t)KPAD_O * DH];

// ---------------- helpers ----------------
__device__ __forceinline__ uint32_t smem_u32(const void* p) {
    uint32_t a;
    asm("{ .reg .u64 t; cvta.to.shared.u64 t, %1; cvt.u32.u64 %0, t; }" : "=r"(a) : "l"(p));
    return a;
}
__device__ __forceinline__ void ldm_x4(uint32_t* r, uint32_t addr) {
    asm volatile("ldmatrix.sync.aligned.m8n8.x4.shared.b16 {%0,%1,%2,%3}, [%4];"
                 : "=r"(r[0]), "=r"(r[1]), "=r"(r[2]), "=r"(r[3]) : "r"(addr));
}
__device__ __forceinline__ void ldm_x2t(uint32_t* r, uint32_t addr) {
    asm volatile("ldmatrix.sync.aligned.m8n8.x2.trans.shared.b16 {%0,%1}, [%2];"
                 : "=r"(r[0]), "=r"(r[1]) : "r"(addr));
}
__device__ __forceinline__ void mma_f16(float* d, const uint32_t* a, const uint32_t* b) {
    asm volatile("mma.sync.aligned.m16n8k16.row.col.f32.f16.f16.f32 "
                 "{%0,%1,%2,%3}, {%4,%5,%6,%7}, {%8,%9}, {%0,%1,%2,%3};"
                 : "+f"(d[0]), "+f"(d[1]), "+f"(d[2]), "+f"(d[3])
                 : "r"(a[0]), "r"(a[1]), "r"(a[2]), "r"(a[3]), "r"(b[0]), "r"(b[1]));
}
__device__ __forceinline__ void cp16(uint32_t dst, const void* src) {
    asm volatile("cp.async.cg.shared.global [%0], [%1], 16;" :: "r"(dst), "l"(src) : "memory");
}
#define CP_COMMIT() asm volatile("cp.async.commit_group;" ::: "memory")
#define CP_WAIT2()  asm volatile("cp.async.wait_group 2;" ::: "memory")

__device__ __forceinline__ uint32_t pack_h2(float x0, float x1) {
    __half2 h = __halves2half2(__float2half_rn(x0), __float2half_rn(x1));
    return *reinterpret_cast<uint32_t*>(&h);
}
__device__ __forceinline__ float2 unpack_h2(uint32_t u) {
    __half2 h = *reinterpret_cast<__half2*>(&u);
    return __half22float2(h);
}

// ---------------- GEMM geometry ----------------
// BM=128, BN=256, BK=64, 256 threads (8 warps, 2m x 4n, warp tile 64x64)
#define A_PITCH 144
#define B_PITCH 528
#define A_BYTES (128 * A_PITCH)          // 18432
#define STAGE_B (A_BYTES + 64 * B_PITCH) // 52224
#define SMEM_TOTAL (4 * STAGE_B)         // 208896

// ---------------------------------------------------------------------------
// Dense fp16 GEMM with fused epilogues.
// MODE 0: v=relu(acc)        -> [STOREH] Hout f16 + fp32 atomicAdd MATnext[dst]
// MODE 1: v=relu(H0h+acc)    -> [STOREH] Hout f16 + fp32 atomicAdd MATnext[dst]
// MODE 2: v=relu(acc+bias)   -> shfl-reduced molecule mean -> plain STG to Fout
// ---------------------------------------------------------------------------
template <int MODE, int KPAD, bool STOREH>
__global__ __launch_bounds__(256, 1)
void mma_gemm(const __half* __restrict__ AH, const __half* __restrict__ W,
              const __half* __restrict__ EPh, const float* __restrict__ bias,
              const int* __restrict__ dst, float* __restrict__ MATnext,
              __half* __restrict__ Hout, float* __restrict__ Fout)
{
    constexpr int NT = KPAD / 64;
    extern __shared__ char smem[];
    __shared__ int s_dst[128];
    const uint32_t sb = smem_u32(smem);
    const int tid = threadIdx.x;
    const int wid = tid >> 5, lane = tid & 31;
    const int wm = wid >> 2, wn = wid & 3;
    const int m0 = blockIdx.y * 128, n0 = blockIdx.x * 256;

    if (MODE != 2 && tid < 128) s_dst[tid] = dst[m0 + tid];

    float acc[4][8][4];
#pragma unroll
    for (int i = 0; i < 4; i++)
#pragma unroll
        for (int j = 0; j < 8; j++)
#pragma unroll
            for (int c = 0; c < 4; c++) acc[i][j][c] = 0.f;

    // ---- async fill of one stage with chunk u ----
    auto issue = [&](int u, int stage) {
        const int kk = u * 64;
        const uint32_t ab = sb + stage * STAGE_B;
        const uint32_t bb = ab + A_BYTES;
#pragma unroll
        for (int p = 0; p < 4; p++) {            // A: 1024 x 16B units
            const int u2 = p * 256 + tid;
            const int row = u2 >> 3, cu = u2 & 7;
            cp16(ab + row * A_PITCH + cu * 16,
                 AH + (size_t)(m0 + row) * KPAD + kk + cu * 8);
        }
#pragma unroll
        for (int p = 0; p < 8; p++) {            // B: 2048 x 16B units
            const int u2 = p * 256 + tid;
            const int row = u2 >> 5, cu = u2 & 31;
            cp16(bb + row * B_PITCH + cu * 16,
                 W + (size_t)(kk + row) * DH + n0 + cu * 8);
        }
    };

    // ---- compute one chunk from a stage ----
    auto compute = [&](int stage) {
        const uint32_t ab = sb + stage * STAGE_B;
        const uint32_t bb = ab + A_BYTES;
        const uint32_t aBase = ab + (uint32_t)(wm * 64 + (lane & 15)) * A_PITCH
                                  + (uint32_t)((lane >> 4) * 16);
        const uint32_t bBase = bb + (uint32_t)(lane & 15) * B_PITCH + (uint32_t)(wn * 128);
#pragma unroll
        for (int ks = 0; ks < 4; ks++) {
            uint32_t a[4][4], b[8][2];
#pragma unroll
            for (int mt = 0; mt < 4; mt++)
                ldm_x4(a[mt], aBase + mt * 16 * A_PITCH + ks * 32);
#pragma unroll
            for (int n = 0; n < 8; n++)
                ldm_x2t(b[n], bBase + ks * 16 * B_PITCH + n * 16);
#pragma unroll
            for (int mt = 0; mt < 4; mt++)
#pragma unroll
                for (int n = 0; n < 8; n++)
                    mma_f16(acc[mt][n], a[mt], b[n]);
        }
    };

    // prologue: up to 3 chunks in flight (4 stages)
    issue(0, 0); CP_COMMIT();
    if (1 < NT) issue(1, 1);
    CP_COMMIT();
    if (2 < NT) issue(2, 2);
    CP_COMMIT();

    for (int t = 0; t < NT; t++) {
        CP_WAIT2();
        __syncthreads();
        if (t + 3 < NT) issue(t + 3, (t + 3) & 3);
        CP_COMMIT();
        compute(t & 3);
    }

    // ---- fused epilogue ----
    const int r0 = lane >> 2, c0 = (lane & 3) * 2;
    if (MODE == 2) {
        // Molecule-mean via shfl butterfly. Warp tile = 64 rows = molecules
        // (m0>>5)+wm*2 (rows 0..31, mt 0-1) and +1 (rows 32..63, mt 2-3).
        float pA[8][2], pB[8][2];
#pragma unroll
        for (int n = 0; n < 8; n++) {
            const int col = n0 + wn * 64 + n * 8 + c0;
            float2 b = *reinterpret_cast<const float2*>(bias + col);
            float a0, a1, s;
            // molecule A: mt 0,1 (rows r0, r0+8, r0+16, r0+24)
            s = 0.f;
            a0 = acc[0][n][0] + b.x; s += a0 > 0.f ? a0 : 0.f;
            a0 = acc[0][n][2] + b.x; s += a0 > 0.f ? a0 : 0.f;
            a0 = acc[1][n][0] + b.x; s += a0 > 0.f ? a0 : 0.f;
            a0 = acc[1][n][2] + b.x; s += a0 > 0.f ? a0 : 0.f;
            pA[n][0] = s;
            s = 0.f;
            a1 = acc[0][n][1] + b.y; s += a1 > 0.f ? a1 : 0.f;
            a1 = acc[0][n][3] + b.y; s += a1 > 0.f ? a1 : 0.f;
            a1 = acc[1][n][1] + b.y; s += a1 > 0.f ? a1 : 0.f;
            a1 = acc[1][n][3] + b.y; s += a1 > 0.f ? a1 : 0.f;
            pA[n][1] = s;
            // molecule B: mt 2,3
            s = 0.f;
            a0 = acc[2][n][0] + b.x; s += a0 > 0.f ? a0 : 0.f;
            a0 = acc[2][n][2] + b.x; s += a0 > 0.f ? a0 : 0.f;
            a0 = acc[3][n][0] + b.x; s += a0 > 0.f ? a0 : 0.f;
            a0 = acc[3][n][2] + b.x; s += a0 > 0.f ? a0 : 0.f;
            pB[n][0] = s;
            s = 0.f;
            a1 = acc[2][n][1] + b.y; s += a1 > 0.f ? a1 : 0.f;
            a1 = acc[2][n][3] + b.y; s += a1 > 0.f ? a1 : 0.f;
            a1 = acc[3][n][1] + b.y; s += a1 > 0.f ? a1 : 0.f;
            a1 = acc[3][n][3] + b.y; s += a1 > 0.f ? a1 : 0.f;
            pB[n][1] = s;
        }
        // butterfly over the 8 lanes sharing a column (lane bits [2:5) = r0)
#pragma unroll
        for (int n = 0; n < 8; n++) {
#pragma unroll
            for (int j = 0; j < 2; j++) {
                float vA = pA[n][j], vB = pB[n][j];
                vA += __shfl_xor_sync(0xFFFFFFFFu, vA, 4);
                vA += __shfl_xor_sync(0xFFFFFFFFu, vA, 8);
                vA += __shfl_xor_sync(0xFFFFFFFFu, vA, 16);
                vB += __shfl_xor_sync(0xFFFFFFFFu, vB, 4);
                vB += __shfl_xor_sync(0xFFFFFFFFu, vB, 8);
                vB += __shfl_xor_sync(0xFFFFFFFFu, vB, 16);
                pA[n][j] = vA; pB[n][j] = vB;
            }
        }
        if (r0 == 0) {                            // lanes 0..3 hold the sums
            const int molA = (m0 >> 5) + wm * 2;
            const float inv = 1.f / 32.f;
#pragma unroll
            for (int n = 0; n < 8; n++) {
                const int col = n0 + wn * 64 + n * 8 + c0;
                *reinterpret_cast<float2*>(Fout + (size_t)molA * DH + col) =
                    make_float2(pA[n][0] * inv, pA[n][1] * inv);
                *reinterpret_cast<float2*>(Fout + (size_t)(molA + 1) * DH + col) =
                    make_float2(pB[n][0] * inv, pB[n][1] * inv);
            }
        }
        return;
    }
#pragma unroll
    for (int mt = 0; mt < 4; mt++) {
#pragma unroll
        for (int n = 0; n < 8; n++) {
            const int lr = wm * 64 + mt * 16 + r0;   // local row 0..127
            const int row = m0 + lr;
            const int col = n0 + wn * 64 + n * 8 + c0;
            float v0 = acc[mt][n][0], v1 = acc[mt][n][1];
            float v2 = acc[mt][n][2], v3 = acc[mt][n][3];
            if (MODE == 1) {
                float2 e0 = unpack_h2(*reinterpret_cast<const uint32_t*>(
                    EPh + (size_t)row * DH + col));
                float2 e1 = unpack_h2(*reinterpret_cast<const uint32_t*>(
                    EPh + (size_t)(row + 8) * DH + col));
                v0 += e0.x; v1 += e0.y; v2 += e1.x; v3 += e1.y;
            }
            v0 = v0 > 0.f ? v0 : 0.f; v1 = v1 > 0.f ? v1 : 0.f;
            v2 = v2 > 0.f ? v2 : 0.f; v3 = v3 > 0.f ? v3 : 0.f;
            if (STOREH) {
                *reinterpret_cast<uint32_t*>(Hout + (size_t)row * DH + col) = pack_h2(v0, v1);
                *reinterpret_cast<uint32_t*>(Hout + (size_t)(row + 8) * DH + col) = pack_h2(v2, v3);
            }
            const size_t d0 = (size_t)s_dst[lr] * DH + col;
            const size_t d1 = (size_t)s_dst[lr + 8] * DH + col;
            atomicAdd(MATnext + d0,     v0);
            atomicAdd(MATnext + d0 + 1, v1);
            atomicAdd(MATnext + d1,     v2);
            atomicAdd(MATnext + d1 + 1, v3);
        }
    }
}

// ---------------------------------------------------------------------------
// Prep kernels: materialize fp16 A operands
// ---------------------------------------------------------------------------
// MP: AH[e][k] = f16(MAT[src[e]][k] - Hh[rev[e]][k]); also zeroes MATnext.
__global__ void prep_mp_k(const float* __restrict__ MAT, const __half* __restrict__ H,
                          const int* __restrict__ src, const int* __restrict__ rev,
                          __half* __restrict__ AH, float* __restrict__ MATnext)
{
    int gid = blockIdx.x * blockDim.x + threadIdx.x;     // NEDGES * 512
    // fused zeroing of MATnext: NATOMS*DH/4 = 8388608 float4 stores
    if (gid < NATOMS * (DH / 4))
        reinterpret_cast<float4*>(MATnext)[gid] = make_float4(0.f, 0.f, 0.f, 0.f);
    int e = gid >> 9, c = gid & 511;
    float4 x = *reinterpret_cast<const float4*>(MAT + (size_t)__ldg(&src[e]) * DH + c * 4);
    uint2 yu = *reinterpret_cast<const uint2*>(H + (size_t)__ldg(&rev[e]) * DH + c * 4);
    float2 y0 = unpack_h2(yu.x), y1 = unpack_h2(yu.y);
    *reinterpret_cast<uint2*>(AH + (size_t)e * DH + c * 4) =
        make_uint2(pack_h2(x.x - y0.x, x.y - y0.y), pack_h2(x.z - y1.x, x.w - y1.y));
}
__global__ void prep_init_k(const float* __restrict__ V, const float* __restrict__ E,
                            const int* __restrict__ src, __half* __restrict__ AH)
{
    int gid = blockIdx.x * blockDim.x + threadIdx.x;     // NEDGES * 32
    int e = gid >> 5, c = gid & 31;
    const int k0 = c * 4;
    float v[4];
#pragma unroll
    for (int j = 0; j < 4; j++) {
        const int k = k0 + j;
        if (k < DV)           v[j] = V[(size_t)__ldg(&src[e]) * DV + k];
        else if (k < DV + DE) v[j] = E[(size_t)e * DE + (k - DV)];
        else                  v[j] = 0.f;
    }
    *reinterpret_cast<uint2*>(AH + (size_t)e * KPAD_I + k0) =
        make_uint2(pack_h2(v[0], v[1]), pack_h2(v[2], v[3]));
}
__global__ void prep_out_k(const float* __restrict__ V, const float* __restrict__ MV,
                           __half* __restrict__ AH)
{
    int gid = blockIdx.x * blockDim.x + threadIdx.x;     // NATOMS * 544
    if (gid >= NATOMS * (KPAD_O / 4)) return;
    int a = gid / (KPAD_O / 4), c = gid % (KPAD_O / 4);
    const int k0 = c * 4;
    float4 x;
    if (k0 < DV) {
        x = make_float4(V[(size_t)a * DV + k0], V[(size_t)a * DV + k0 + 1],
                        V[(size_t)a * DV + k0 + 2], V[(size_t)a * DV + k0 + 3]);
    } else if (k0 < DV + DH) {
        x = *reinterpret_cast<const float4*>(MV + (size_t)a * DH + (k0 - DV));
    } else {
        x = make_float4(0.f, 0.f, 0.f, 0.f);
    }
    *reinterpret_cast<uint2*>(AH + (size_t)a * KPAD_O + k0) =
        make_uint2(pack_h2(x.x, x.y), pack_h2(x.z, x.w));
}

// Weight convert to fp16 (keeps [K][2048] layout, zero-pads to Kpad rows)
__global__ void convert_w_k(const float* __restrict__ W,
                            __half* __restrict__ Oh, int K, int Kpad) {
    int idx = blockIdx.x * blockDim.x + threadIdx.x;
    int e0 = idx * 4;
    int k = e0 >> 11;
    if (k >= Kpad) return;
    float4 v = (k < K) ? *reinterpret_cast<const float4*>(W + e0)
                       : make_float4(0.f, 0.f, 0.f, 0.f);
    *reinterpret_cast<uint2*>(Oh + e0) =
        make_uint2(pack_h2(v.x, v.y), pack_h2(v.z, v.w));
}

// ---------------- aux kernels ----------------
__global__ void zero_k(float4* __restrict__ p, int n4) {
    int gid = blockIdx.x * blockDim.x + threadIdx.x;
    if (gid < n4) p[gid] = make_float4(0.f, 0.f, 0.f, 0.f);
}

extern "C" void kernel_launch(void* const* d_in, const int* in_sizes, int n_in,
                              void* d_out, int out_size)
{
    const float* V    = (const float*)d_in[0];
    const float* E    = (const float*)d_in[1];
    const int*   esrc = (const int*)d_in[2];
    const int*   edst = (const int*)d_in[3];
    const int*   erev = (const int*)d_in[4];
    const float* W_i  = (const float*)d_in[6];
    const float* W_h  = (const float*)d_in[7];
    const float* W_o  = (const float*)d_in[8];
    const float* b_o  = (const float*)d_in[9];
    float* out = (float*)d_out;

    float *MA, *MB;
    cudaGetSymbolAddress((void**)&MA, g_MA);
    cudaGetSymbolAddress((void**)&MB, g_MB);
    __half *H0h, *HFA, *HFB, *AH, *Wi, *Wh, *Wo;
    cudaGetSymbolAddress((void**)&H0h, g_H0h);
    cudaGetSymbolAddress((void**)&HFA, g_HFA);
    cudaGetSymbolAddress((void**)&HFB, g_HFB);
    cudaGetSymbolAddress((void**)&AH,  g_AH);
    cudaGetSymbolAddress((void**)&Wi,  g_Wi);
    cudaGetSymbolAddress((void**)&Wh,  g_Wh);
    cudaGetSymbolAddress((void**)&Wo,  g_Wo);

    cudaFuncSetAttribute(mma_gemm<0, KPAD_I, true>,
                         cudaFuncAttributeMaxDynamicSharedMemorySize, SMEM_TOTAL);
    cudaFuncSetAttribute(mma_gemm<1, DH, true>,
                         cudaFuncAttributeMaxDynamicSharedMemorySize, SMEM_TOTAL);
    cudaFuncSetAttribute(mma_gemm<1, DH, false>,
                         cudaFuncAttributeMaxDynamicSharedMemorySize, SMEM_TOTAL);
    cudaFuncSetAttribute(mma_gemm<2, KPAD_O, false>,
                         cudaFuncAttributeMaxDynamicSharedMemorySize, SMEM_TOTAL);

    const dim3 blk(256);
    convert_w_k<<<(KPAD_I * DH / 4 + 255) / 256, blk>>>(W_i, Wi, DV + DE, KPAD_I);
    convert_w_k<<<(DH * DH / 4 + 255) / 256, blk>>>(W_h, Wh, DH, DH);
    convert_w_k<<<(KPAD_O * DH / 4 + 255) / 256, blk>>>(W_o, Wo, DV + DH, KPAD_O);

    const dim3 gE(DH / 256, NEDGES / 128);   // (8, 256)
    const dim3 gA(DH / 256, NATOMS / 128);   // (8, 128)
    const int matN4  = NATOMS * (DH / 4);
    const int zeroBl = (matN4 + 255) / 256;

    // H0 = relu([V[src]; E] @ W_i); epilogue scatters H0 into MA
    prep_init_k<<<(NEDGES * 32) / 256, blk>>>(V, E, esrc, AH);
    zero_k<<<zeroBl, blk>>>((float4*)MA, matN4);
    mma_gemm<0, KPAD_I, true><<<gE, blk, SMEM_TOTAL>>>(AH, Wi, nullptr, nullptr,
                                                       edst, MA, H0h, nullptr);

    const __half* Hcur = H0h;
    for (int it = 0; it < 4; it++) {
        float* MATcur  = (it & 1) ? MB : MA;
        float* MATnext = (it & 1) ? MA : MB;
        __half* Hnext  = (it & 1) ? HFB : HFA;
        prep_mp_k<<<(NEDGES * 512) / 256, blk>>>(MATcur, Hcur, esrc, erev, AH, MATnext);
        if (it < 3)
            mma_gemm<1, DH, true><<<gE, blk, SMEM_TOTAL>>>(AH, Wh, H0h, nullptr,
                                                           edst, MATnext, Hnext, nullptr);
        else  // last MP layer: H output is dead, only the scatter matters
            mma_gemm<1, DH, false><<<gE, blk, SMEM_TOTAL>>>(AH, Wh, H0h, nullptr,
                                                            edst, MATnext, Hnext, nullptr);
        Hcur = Hnext;
    }

    // final MAT is MA; fingerprint = molecule-mean of relu([V;M_v]@W_o + b_o),
    // reduced in-epilogue (shfl butterfly, plain stores, no HV buffer)
    prep_out_k<<<(NATOMS * (KPAD_O / 4) + 255) / 256, blk>>>(V, MA, AH);
    mma_gemm<2, KPAD_O, false><<<gA, blk, SMEM_TOTAL>>>(AH, Wo, nullptr, b_o,
                                                        nullptr, nullptr, nullptr, out);
}

// round 17
// speedup vs baseline: 1.0705x; 1.0067x over previous
#include <cuda_runtime.h>
#include <cuda_fp16.h>
#include <cstdint>
#include <cstddef>

#define NATOMS 16384
#define NEDGES 32768
#define NMOLS  512
#define DV     72
#define DE     14
#define DH     2048

#define KPAD_I 128
#define KPAD_O 2176

// ---------------- scratch ----------------
__device__ __half g_H0h[(size_t)NEDGES * DH];   // H0 (fp16)
__device__ __half g_HFA[(size_t)NEDGES * DH];   // H ping
__device__ __half g_HFB[(size_t)NEDGES * DH];   // H pong
__device__ float  g_MA[(size_t)NATOMS * DH];    // MAT ping
__device__ float  g_MB[(size_t)NATOMS * DH];    // MAT pong
__device__ __half g_AH[(size_t)NEDGES * DH];    // fp16 A operand
__device__ __half g_Wi[(size_t)KPAD_I * DH];
__device__ __half g_Wh[(size_t)DH * DH];
__device__ __half g_Wo[(size_t)KPAD_O * DH];

// ---------------- helpers ----------------
__device__ __forceinline__ uint32_t smem_u32(const void* p) {
    uint32_t a;
    asm("{ .reg .u64 t; cvta.to.shared.u64 t, %1; cvt.u32.u64 %0, t; }" : "=r"(a) : "l"(p));
    return a;
}
__device__ __forceinline__ void ldm_x4(uint32_t* r, uint32_t addr) {
    asm volatile("ldmatrix.sync.aligned.m8n8.x4.shared.b16 {%0,%1,%2,%3}, [%4];"
                 : "=r"(r[0]), "=r"(r[1]), "=r"(r[2]), "=r"(r[3]) : "r"(addr));
}
__device__ __forceinline__ void ldm_x2t(uint32_t* r, uint32_t addr) {
    asm volatile("ldmatrix.sync.aligned.m8n8.x2.trans.shared.b16 {%0,%1}, [%2];"
                 : "=r"(r[0]), "=r"(r[1]) : "r"(addr));
}
__device__ __forceinline__ void mma_f16(float* d, const uint32_t* a, const uint32_t* b) {
    asm volatile("mma.sync.aligned.m16n8k16.row.col.f32.f16.f16.f32 "
                 "{%0,%1,%2,%3}, {%4,%5,%6,%7}, {%8,%9}, {%0,%1,%2,%3};"
                 : "+f"(d[0]), "+f"(d[1]), "+f"(d[2]), "+f"(d[3])
                 : "r"(a[0]), "r"(a[1]), "r"(a[2]), "r"(a[3]), "r"(b[0]), "r"(b[1]));
}
__device__ __forceinline__ void cp16(uint32_t dst, const void* src) {
    asm volatile("cp.async.cg.shared.global [%0], [%1], 16;" :: "r"(dst), "l"(src) : "memory");
}
#define CP_COMMIT() asm volatile("cp.async.commit_group;" ::: "memory")
#define CP_WAIT2()  asm volatile("cp.async.wait_group 2;" ::: "memory")

__device__ __forceinline__ uint32_t pack_h2(float x0, float x1) {
    __half2 h = __halves2half2(__float2half_rn(x0), __float2half_rn(x1));
    return *reinterpret_cast<uint32_t*>(&h);
}
__device__ __forceinline__ float2 unpack_h2(uint32_t u) {
    __half2 h = *reinterpret_cast<__half2*>(&u);
    return __half22float2(h);
}
__device__ __forceinline__ void red_v2(float* addr, float a, float b) {
    asm volatile("red.global.add.v2.f32 [%0], {%1, %2};"
                 :: "l"(addr), "f"(a), "f"(b) : "memory");
}

// ---------------- GEMM geometry ----------------
// BM=128, BN=256, BK=64, 256 threads (8 warps, 2m x 4n, warp tile 64x64)
#define A_PITCH 144
#define B_PITCH 528
#define A_BYTES (128 * A_PITCH)          // 18432
#define STAGE_B (A_BYTES + 64 * B_PITCH) // 52224
#define SMEM_TOTAL (4 * STAGE_B)         // 208896

// ---------------------------------------------------------------------------
// Dense fp16 GEMM with fused epilogues.
// MODE 0: v=relu(acc)        -> [STOREH] Hout f16 + red.v2.f32 MATnext[dst]
// MODE 1: v=relu(H0h+acc)    -> [STOREH] Hout f16 + red.v2.f32 MATnext[dst]
// MODE 2: v=relu(acc+bias)   -> shfl-reduced molecule mean -> plain STG to Fout
// ---------------------------------------------------------------------------
template <int MODE, int KPAD, bool STOREH>
__global__ __launch_bounds__(256, 1)
void mma_gemm(const __half* __restrict__ AH, const __half* __restrict__ W,
              const __half* __restrict__ EPh, const float* __restrict__ bias,
              const int* __restrict__ dst, float* __restrict__ MATnext,
              __half* __restrict__ Hout, float* __restrict__ Fout)
{
    constexpr int NT = KPAD / 64;
    extern __shared__ char smem[];
    __shared__ int s_dst[128];
    const uint32_t sb = smem_u32(smem);
    const int tid = threadIdx.x;
    const int wid = tid >> 5, lane = tid & 31;
    const int wm = wid >> 2, wn = wid & 3;
    const int m0 = blockIdx.y * 128, n0 = blockIdx.x * 256;

    if (MODE != 2 && tid < 128) s_dst[tid] = dst[m0 + tid];

    float acc[4][8][4];
#pragma unroll
    for (int i = 0; i < 4; i++)
#pragma unroll
        for (int j = 0; j < 8; j++)
#pragma unroll
            for (int c = 0; c < 4; c++) acc[i][j][c] = 0.f;

    // ---- async fill of one stage with chunk u ----
    auto issue = [&](int u, int stage) {
        const int kk = u * 64;
        const uint32_t ab = sb + stage * STAGE_B;
        const uint32_t bb = ab + A_BYTES;
#pragma unroll
        for (int p = 0; p < 4; p++) {            // A: 1024 x 16B units
            const int u2 = p * 256 + tid;
            const int row = u2 >> 3, cu = u2 & 7;
            cp16(ab + row * A_PITCH + cu * 16,
                 AH + (size_t)(m0 + row) * KPAD + kk + cu * 8);
        }
#pragma unroll
        for (int p = 0; p < 8; p++) {            // B: 2048 x 16B units
            const int u2 = p * 256 + tid;
            const int row = u2 >> 5, cu = u2 & 31;
            cp16(bb + row * B_PITCH + cu * 16,
                 W + (size_t)(kk + row) * DH + n0 + cu * 8);
        }
    };

    // ---- compute one chunk from a stage ----
    auto compute = [&](int stage) {
        const uint32_t ab = sb + stage * STAGE_B;
        const uint32_t bb = ab + A_BYTES;
        const uint32_t aBase = ab + (uint32_t)(wm * 64 + (lane & 15)) * A_PITCH
                                  + (uint32_t)((lane >> 4) * 16);
        const uint32_t bBase = bb + (uint32_t)(lane & 15) * B_PITCH + (uint32_t)(wn * 128);
#pragma unroll
        for (int ks = 0; ks < 4; ks++) {
            uint32_t a[4][4], b[8][2];
#pragma unroll
            for (int mt = 0; mt < 4; mt++)
                ldm_x4(a[mt], aBase + mt * 16 * A_PITCH + ks * 32);
#pragma unroll
            for (int n = 0; n < 8; n++)
                ldm_x2t(b[n], bBase + ks * 16 * B_PITCH + n * 16);
#pragma unroll
            for (int mt = 0; mt < 4; mt++)
#pragma unroll
                for (int n = 0; n < 8; n++)
                    mma_f16(acc[mt][n], a[mt], b[n]);
        }
    };

    // prologue: up to 3 chunks in flight (4 stages)
    issue(0, 0); CP_COMMIT();
    if (1 < NT) issue(1, 1);
    CP_COMMIT();
    if (2 < NT) issue(2, 2);
    CP_COMMIT();

    for (int t = 0; t < NT; t++) {
        CP_WAIT2();
        __syncthreads();
        if (t + 3 < NT) issue(t + 3, (t + 3) & 3);
        CP_COMMIT();
        compute(t & 3);
    }

    // ---- fused epilogue ----
    const int r0 = lane >> 2, c0 = (lane & 3) * 2;
    if (MODE == 2) {
        // Molecule-mean via shfl butterfly. Warp tile = 64 rows = molecules
        // (m0>>5)+wm*2 (rows 0..31, mt 0-1) and +1 (rows 32..63, mt 2-3).
        float pA[8][2], pB[8][2];
#pragma unroll
        for (int n = 0; n < 8; n++) {
            const int col = n0 + wn * 64 + n * 8 + c0;
            float2 b = *reinterpret_cast<const float2*>(bias + col);
            float a0, a1, s;
            s = 0.f;
            a0 = acc[0][n][0] + b.x; s += a0 > 0.f ? a0 : 0.f;
            a0 = acc[0][n][2] + b.x; s += a0 > 0.f ? a0 : 0.f;
            a0 = acc[1][n][0] + b.x; s += a0 > 0.f ? a0 : 0.f;
            a0 = acc[1][n][2] + b.x; s += a0 > 0.f ? a0 : 0.f;
            pA[n][0] = s;
            s = 0.f;
            a1 = acc[0][n][1] + b.y; s += a1 > 0.f ? a1 : 0.f;
            a1 = acc[0][n][3] + b.y; s += a1 > 0.f ? a1 : 0.f;
            a1 = acc[1][n][1] + b.y; s += a1 > 0.f ? a1 : 0.f;
            a1 = acc[1][n][3] + b.y; s += a1 > 0.f ? a1 : 0.f;
            pA[n][1] = s;
            s = 0.f;
            a0 = acc[2][n][0] + b.x; s += a0 > 0.f ? a0 : 0.f;
            a0 = acc[2][n][2] + b.x; s += a0 > 0.f ? a0 : 0.f;
            a0 = acc[3][n][0] + b.x; s += a0 > 0.f ? a0 : 0.f;
            a0 = acc[3][n][2] + b.x; s += a0 > 0.f ? a0 : 0.f;
            pB[n][0] = s;
            s = 0.f;
            a1 = acc[2][n][1] + b.y; s += a1 > 0.f ? a1 : 0.f;
            a1 = acc[2][n][3] + b.y; s += a1 > 0.f ? a1 : 0.f;
            a1 = acc[3][n][1] + b.y; s += a1 > 0.f ? a1 : 0.f;
            a1 = acc[3][n][3] + b.y; s += a1 > 0.f ? a1 : 0.f;
            pB[n][1] = s;
        }
#pragma unroll
        for (int n = 0; n < 8; n++) {
#pragma unroll
            for (int j = 0; j < 2; j++) {
                float vA = pA[n][j], vB = pB[n][j];
                vA += __shfl_xor_sync(0xFFFFFFFFu, vA, 4);
                vA += __shfl_xor_sync(0xFFFFFFFFu, vA, 8);
                vA += __shfl_xor_sync(0xFFFFFFFFu, vA, 16);
                vB += __shfl_xor_sync(0xFFFFFFFFu, vB, 4);
                vB += __shfl_xor_sync(0xFFFFFFFFu, vB, 8);
                vB += __shfl_xor_sync(0xFFFFFFFFu, vB, 16);
                pA[n][j] = vA; pB[n][j] = vB;
            }
        }
        if (r0 == 0) {                            // lanes 0..3 hold the sums
            const int molA = (m0 >> 5) + wm * 2;
            const float inv = 1.f / 32.f;
#pragma unroll
            for (int n = 0; n < 8; n++) {
                const int col = n0 + wn * 64 + n * 8 + c0;
                *reinterpret_cast<float2*>(Fout + (size_t)molA * DH + col) =
                    make_float2(pA[n][0] * inv, pA[n][1] * inv);
                *reinterpret_cast<float2*>(Fout + (size_t)(molA + 1) * DH + col) =
                    make_float2(pB[n][0] * inv, pB[n][1] * inv);
            }
        }
        return;
    }
#pragma unroll
    for (int mt = 0; mt < 4; mt++) {
#pragma unroll
        for (int n = 0; n < 8; n++) {
            const int lr = wm * 64 + mt * 16 + r0;   // local row 0..127
            const int row = m0 + lr;
            const int col = n0 + wn * 64 + n * 8 + c0;
            float v0 = acc[mt][n][0], v1 = acc[mt][n][1];
            float v2 = acc[mt][n][2], v3 = acc[mt][n][3];
            if (MODE == 1) {
                float2 e0 = unpack_h2(*reinterpret_cast<const uint32_t*>(
                    EPh + (size_t)row * DH + col));
                float2 e1 = unpack_h2(*reinterpret_cast<const uint32_t*>(
                    EPh + (size_t)(row + 8) * DH + col));
                v0 += e0.x; v1 += e0.y; v2 += e1.x; v3 += e1.y;
            }
            v0 = v0 > 0.f ? v0 : 0.f; v1 = v1 > 0.f ? v1 : 0.f;
            v2 = v2 > 0.f ? v2 : 0.f; v3 = v3 > 0.f ? v3 : 0.f;
            if (STOREH) {
                *reinterpret_cast<uint32_t*>(Hout + (size_t)row * DH + col) = pack_h2(v0, v1);
                *reinterpret_cast<uint32_t*>(Hout + (size_t)(row + 8) * DH + col) = pack_h2(v2, v3);
            }
            red_v2(MATnext + (size_t)s_dst[lr] * DH + col,     v0, v1);
            red_v2(MATnext + (size_t)s_dst[lr + 8] * DH + col, v2, v3);
        }
    }
}

// ---------------------------------------------------------------------------
// Prep kernels: materialize fp16 A operands
// ---------------------------------------------------------------------------
// MP: AH[e][k] = f16(MAT[src[e]][k] - Hh[rev[e]][k]); also zeroes MATnext.
__global__ void prep_mp_k(const float* __restrict__ MAT, const __half* __restrict__ H,
                          const int* __restrict__ src, const int* __restrict__ rev,
                          __half* __restrict__ AH, float* __restrict__ MATnext)
{
    int gid = blockIdx.x * blockDim.x + threadIdx.x;     // NEDGES * 512
    // fused zeroing of MATnext: NATOMS*DH/4 = 8388608 float4 stores
    if (gid < NATOMS * (DH / 4))
        reinterpret_cast<float4*>(MATnext)[gid] = make_float4(0.f, 0.f, 0.f, 0.f);
    int e = gid >> 9, c = gid & 511;
    float4 x = *reinterpret_cast<const float4*>(MAT + (size_t)__ldg(&src[e]) * DH + c * 4);
    uint2 yu = *reinterpret_cast<const uint2*>(H + (size_t)__ldg(&rev[e]) * DH + c * 4);
    float2 y0 = unpack_h2(yu.x), y1 = unpack_h2(yu.y);
    *reinterpret_cast<uint2*>(AH + (size_t)e * DH + c * 4) =
        make_uint2(pack_h2(x.x - y0.x, x.y - y0.y), pack_h2(x.z - y1.x, x.w - y1.y));
}
__global__ void prep_init_k(const float* __restrict__ V, const float* __restrict__ E,
                            const int* __restrict__ src, __half* __restrict__ AH)
{
    int gid = blockIdx.x * blockDim.x + threadIdx.x;     // NEDGES * 32
    int e = gid >> 5, c = gid & 31;
    const int k0 = c * 4;
    float v[4];
#pragma unroll
    for (int j = 0; j < 4; j++) {
        const int k = k0 + j;
        if (k < DV)           v[j] = V[(size_t)__ldg(&src[e]) * DV + k];
        else if (k < DV + DE) v[j] = E[(size_t)e * DE + (k - DV)];
        else                  v[j] = 0.f;
    }
    *reinterpret_cast<uint2*>(AH + (size_t)e * KPAD_I + k0) =
        make_uint2(pack_h2(v[0], v[1]), pack_h2(v[2], v[3]));
}
__global__ void prep_out_k(const float* __restrict__ V, const float* __restrict__ MV,
                           __half* __restrict__ AH)
{
    int gid = blockIdx.x * blockDim.x + threadIdx.x;     // NATOMS * 544
    if (gid >= NATOMS * (KPAD_O / 4)) return;
    int a = gid / (KPAD_O / 4), c = gid % (KPAD_O / 4);
    const int k0 = c * 4;
    float4 x;
    if (k0 < DV) {
        x = make_float4(V[(size_t)a * DV + k0], V[(size_t)a * DV + k0 + 1],
                        V[(size_t)a * DV + k0 + 2], V[(size_t)a * DV + k0 + 3]);
    } else if (k0 < DV + DH) {
        x = *reinterpret_cast<const float4*>(MV + (size_t)a * DH + (k0 - DV));
    } else {
        x = make_float4(0.f, 0.f, 0.f, 0.f);
    }
    *reinterpret_cast<uint2*>(AH + (size_t)a * KPAD_O + k0) =
        make_uint2(pack_h2(x.x, x.y), pack_h2(x.z, x.w));
}

// Weight convert to fp16 (keeps [K][2048] layout, zero-pads to Kpad rows)
__global__ void convert_w_k(const float* __restrict__ W,
                            __half* __restrict__ Oh, int K, int Kpad) {
    int idx = blockIdx.x * blockDim.x + threadIdx.x;
    int e0 = idx * 4;
    int k = e0 >> 11;
    if (k >= Kpad) return;
    float4 v = (k < K) ? *reinterpret_cast<const float4*>(W + e0)
                       : make_float4(0.f, 0.f, 0.f, 0.f);
    *reinterpret_cast<uint2*>(Oh + e0) =
        make_uint2(pack_h2(v.x, v.y), pack_h2(v.z, v.w));
}

// ---------------- aux kernels ----------------
__global__ void zero_k(float4* __restrict__ p, int n4) {
    int gid = blockIdx.x * blockDim.x + threadIdx.x;
    if (gid < n4) p[gid] = make_float4(0.f, 0.f, 0.f, 0.f);
}

extern "C" void kernel_launch(void* const* d_in, const int* in_sizes, int n_in,
                              void* d_out, int out_size)
{
    const float* V    = (const float*)d_in[0];
    const float* E    = (const float*)d_in[1];
    const int*   esrc = (const int*)d_in[2];
    const int*   edst = (const int*)d_in[3];
    const int*   erev = (const int*)d_in[4];
    const float* W_i  = (const float*)d_in[6];
    const float* W_h  = (const float*)d_in[7];
    const float* W_o  = (const float*)d_in[8];
    const float* b_o  = (const float*)d_in[9];
    float* out = (float*)d_out;

    float *MA, *MB;
    cudaGetSymbolAddress((void**)&MA, g_MA);
    cudaGetSymbolAddress((void**)&MB, g_MB);
    __half *H0h, *HFA, *HFB, *AH, *Wi, *Wh, *Wo;
    cudaGetSymbolAddress((void**)&H0h, g_H0h);
    cudaGetSymbolAddress((void**)&HFA, g_HFA);
    cudaGetSymbolAddress((void**)&HFB, g_HFB);
    cudaGetSymbolAddress((void**)&AH,  g_AH);
    cudaGetSymbolAddress((void**)&Wi,  g_Wi);
    cudaGetSymbolAddress((void**)&Wh,  g_Wh);
    cudaGetSymbolAddress((void**)&Wo,  g_Wo);

    cudaFuncSetAttribute(mma_gemm<0, KPAD_I, true>,
                         cudaFuncAttributeMaxDynamicSharedMemorySize, SMEM_TOTAL);
    cudaFuncSetAttribute(mma_gemm<1, DH, true>,
                         cudaFuncAttributeMaxDynamicSharedMemorySize, SMEM_TOTAL);
    cudaFuncSetAttribute(mma_gemm<1, DH, false>,
                         cudaFuncAttributeMaxDynamicSharedMemorySize, SMEM_TOTAL);
    cudaFuncSetAttribute(mma_gemm<2, KPAD_O, false>,
                         cudaFuncAttributeMaxDynamicSharedMemorySize, SMEM_TOTAL);

    const dim3 blk(256);
    convert_w_k<<<(KPAD_I * DH / 4 + 255) / 256, blk>>>(W_i, Wi, DV + DE, KPAD_I);
    convert_w_k<<<(DH * DH / 4 + 255) / 256, blk>>>(W_h, Wh, DH, DH);
    convert_w_k<<<(KPAD_O * DH / 4 + 255) / 256, blk>>>(W_o, Wo, DV + DH, KPAD_O);

    const dim3 gE(DH / 256, NEDGES / 128);   // (8, 256)
    const dim3 gA(DH / 256, NATOMS / 128);   // (8, 128)
    const int matN4  = NATOMS * (DH / 4);
    const int zeroBl = (matN4 + 255) / 256;

    // H0 = relu([V[src]; E] @ W_i); epilogue scatters H0 into MA
    prep_init_k<<<(NEDGES * 32) / 256, blk>>>(V, E, esrc, AH);
    zero_k<<<zeroBl, blk>>>((float4*)MA, matN4);
    mma_gemm<0, KPAD_I, true><<<gE, blk, SMEM_TOTAL>>>(AH, Wi, nullptr, nullptr,
                                                       edst, MA, H0h, nullptr);

    const __half* Hcur = H0h;
    for (int it = 0; it < 4; it++) {
        float* MATcur  = (it & 1) ? MB : MA;
        float* MATnext = (it & 1) ? MA : MB;
        __half* Hnext  = (it & 1) ? HFB : HFA;
        prep_mp_k<<<(NEDGES * 512) / 256, blk>>>(MATcur, Hcur, esrc, erev, AH, MATnext);
        if (it < 3)
            mma_gemm<1, DH, true><<<gE, blk, SMEM_TOTAL>>>(AH, Wh, H0h, nullptr,
                                                           edst, MATnext, Hnext, nullptr);
        else  // last MP layer: H output is dead, only the scatter matters
            mma_gemm<1, DH, false><<<gE, blk, SMEM_TOTAL>>>(AH, Wh, H0h, nullptr,
                                                            edst, MATnext, Hnext, nullptr);
        Hcur = Hnext;
    }

    // final MAT is MA; fingerprint = molecule-mean of relu([V;M_v]@W_o + b_o),
    // reduced in-epilogue (shfl butterfly, plain stores, no HV buffer)
    prep_out_k<<<(NATOMS * (KPAD_O / 4) + 255) / 256, blk>>>(V, MA, AH);
    mma_gemm<2, KPAD_O, false><<<gA, blk, SMEM_TOTAL>>>(AH, Wo, nullptr, b_o,
                                                        nullptr, nullptr, nullptr, out);
}